// round 2
// baseline (speedup 1.0000x reference)
#include <cuda_runtime.h>
#include <cuda_fp16.h>
#include <cstdint>
#include <cstddef>

#define DEVI __device__ __forceinline__

static constexpr int M_DIM = 8192;
static constexpr int N_DIM = 4096;
static constexpr int K_DIM = 4096;

static constexpr int BM = 256;
static constexpr int BN = 128;
static constexpr int BK = 32;
static constexpr int NTHREADS = 512;
static constexpr int STAGES = 4;
static constexpr int NKITER = K_DIM / BK;       // 128

static constexpr int PITCH = BK + 8;            // 40 halves = 80 bytes, conflict-free ldmatrix
static constexpr int A_STAGE_BYTES = BM * PITCH * 2;   // 20480
static constexpr int B_STAGE_BYTES = BN * PITCH * 2;   // 10240
static constexpr int STAGE_BYTES = A_STAGE_BYTES + B_STAGE_BYTES;  // 30720
static constexpr int SMEM_TOTAL = STAGES * STAGE_BYTES;            // 122880

// Scratch: x in fp16, W quantized*127 (exact integer in fp16), transposed to [N,K] K-major.
__device__ __half g_xh[(size_t)M_DIM * K_DIM];
__device__ __half g_wt[(size_t)N_DIM * K_DIM];

// ---------------- helpers ----------------
DEVI uint32_t smem_u32(const void* p) {
    uint32_t a;
    asm("{ .reg .u64 t; cvta.to.shared.u64 t, %1; cvt.u32.u64 %0, t; }" : "=r"(a) : "l"(p));
    return a;
}

#define CPA16(dst, src) \
    asm volatile("cp.async.cg.shared.global [%0], [%1], 16;" :: "r"(dst), "l"(src) : "memory")
#define CPA_COMMIT() asm volatile("cp.async.commit_group;" ::: "memory")
#define CPA_WAIT(n)  asm volatile("cp.async.wait_group %0;" :: "n"(n) : "memory")

#define LDSM4(r, addr) \
    asm volatile("ldmatrix.sync.aligned.m8n8.x4.shared.b16 {%0,%1,%2,%3}, [%4];" \
        : "=r"((r)[0]), "=r"((r)[1]), "=r"((r)[2]), "=r"((r)[3]) : "r"(addr))

DEVI void mma16816(float* c, const uint32_t* a, uint32_t b0, uint32_t b1) {
    asm volatile(
        "mma.sync.aligned.m16n8k16.row.col.f32.f16.f16.f32 "
        "{%0,%1,%2,%3}, {%4,%5,%6,%7}, {%8,%9}, {%0,%1,%2,%3};"
        : "+f"(c[0]), "+f"(c[1]), "+f"(c[2]), "+f"(c[3])
        : "r"(a[0]), "r"(a[1]), "r"(a[2]), "r"(a[3]), "r"(b0), "r"(b1));
}

// ---------------- preprocessing ----------------

// x fp32 -> fp16, 8 elems/thread
__global__ void __launch_bounds__(256) convert_x_kernel(const float* __restrict__ X) {
    size_t i = ((size_t)blockIdx.x * 256 + threadIdx.x) * 8;
    float4 a = *reinterpret_cast<const float4*>(X + i);
    float4 b = *reinterpret_cast<const float4*>(X + i + 4);
    __half2 p0 = __floats2half2_rn(a.x, a.y);
    __half2 p1 = __floats2half2_rn(a.z, a.w);
    __half2 p2 = __floats2half2_rn(b.x, b.y);
    __half2 p3 = __floats2half2_rn(b.z, b.w);
    uint4 u;
    u.x = *reinterpret_cast<uint32_t*>(&p0);
    u.y = *reinterpret_cast<uint32_t*>(&p1);
    u.z = *reinterpret_cast<uint32_t*>(&p2);
    u.w = *reinterpret_cast<uint32_t*>(&p3);
    *reinterpret_cast<uint4*>(g_xh + i) = u;
}

// W [K,N] fp32 -> g_wt [N,K] fp16 = round(clip(w)*127) via smem-tiled transpose
__global__ void __launch_bounds__(256) quant_w_kernel(const float* __restrict__ W) {
    __shared__ __half tile[64][66];
    int t = threadIdx.x;
    int n0 = blockIdx.x * 64;
    int k0 = blockIdx.y * 64;
    int r = t >> 6;        // 0..3
    int c = t & 63;        // 0..63
#pragma unroll
    for (int rr = 0; rr < 16; rr++) {
        int k = r + rr * 4;
        float w = W[(size_t)(k0 + k) * N_DIM + n0 + c];
        w = fminf(fmaxf(w, -1.0f), 1.0f);
        tile[k][c] = __float2half_rn(rintf(w * 127.0f));
    }
    __syncthreads();
#pragma unroll
    for (int ww = 0; ww < 16; ww++) {
        int nl = r + ww * 4;
        g_wt[(size_t)(n0 + nl) * K_DIM + k0 + c] = tile[c][nl];
    }
}

// ---------------- GEMM ----------------

DEVI void load_stage(uint32_t sbase, int buf,
                     const __half* __restrict__ gA, const __half* __restrict__ gB,
                     int k0, int tid) {
    uint32_t sA = sbase + buf * STAGE_BYTES;
    uint32_t sB = sA + A_STAGE_BYTES;
    const __half* a = gA + k0;
    const __half* b = gB + k0;
#pragma unroll
    for (int i = 0; i < 2; i++) {
        int id = tid + i * NTHREADS;       // 0..1023
        int r = id >> 2;
        int c = id & 3;
        CPA16(sA + (uint32_t)(r * (PITCH * 2) + c * 16), a + (size_t)r * K_DIM + c * 8);
    }
    {
        int r = tid >> 2;
        int c = tid & 3;
        CPA16(sB + (uint32_t)(r * (PITCH * 2) + c * 16), b + (size_t)r * K_DIM + c * 8);
    }
}

__global__ void __launch_bounds__(NTHREADS, 1) pwb_gemm_kernel(
    float* __restrict__ out, const float* __restrict__ bias) {
    extern __shared__ char smem[];
    uint32_t sbase = smem_u32(smem);

    int tid = threadIdx.x;
    int lane = tid & 31;
    int w = tid >> 5;                       // 0..15
    int warp_m = (w >> 2) * 64;             // 4 warps in M
    int warp_n = (w & 3) * 32;              // 4 warps in N

    int ctaM = (int)(blockIdx.x >> 5) * BM; // 32 M tiles
    int ctaN = (int)(blockIdx.x & 31) * BN; // 32 N tiles

    const __half* gA = g_xh + (size_t)ctaM * K_DIM;
    const __half* gB = g_wt + (size_t)ctaN * K_DIM;

    // ldmatrix per-lane address components
    uint32_t aRowOff = (uint32_t)(warp_m + (lane & 15)) * (PITCH * 2) + ((lane >> 4) << 4);
    uint32_t bMat = lane >> 3;
    uint32_t bRowOff = (uint32_t)(warp_n + ((bMat >> 1) << 3) + (lane & 7)) * (PITCH * 2)
                       + ((bMat & 1) << 4);

    float acc[4][4][4];
#pragma unroll
    for (int mi = 0; mi < 4; mi++)
#pragma unroll
        for (int nj = 0; nj < 4; nj++)
#pragma unroll
            for (int e = 0; e < 4; e++) acc[mi][nj][e] = 0.0f;

    // prologue: prefetch STAGES-1 stages
#pragma unroll
    for (int s = 0; s < STAGES - 1; s++) {
        load_stage(sbase, s, gA, gB, s * BK, tid);
        CPA_COMMIT();
    }
    CPA_WAIT(STAGES - 2);
    __syncthreads();

    for (int it = 0; it < NKITER; it++) {
        int buf = it & (STAGES - 1);

        // issue prefetch for stage it+STAGES-1
        if (it + STAGES - 1 < NKITER) {
            load_stage(sbase, (it + STAGES - 1) & (STAGES - 1), gA, gB,
                       (it + STAGES - 1) * BK, tid);
        }
        CPA_COMMIT();

        // compute on stage `it`
        uint32_t sA = sbase + buf * STAGE_BYTES;
        uint32_t sB = sA + A_STAGE_BYTES;
#pragma unroll
        for (int ks = 0; ks < 2; ks++) {
            uint32_t afr[4][4];
            uint32_t bfr[2][4];
#pragma unroll
            for (int mi = 0; mi < 4; mi++)
                LDSM4(afr[mi], sA + aRowOff + (uint32_t)(mi * 16 * PITCH * 2) + ks * 32);
#pragma unroll
            for (int g = 0; g < 2; g++)
                LDSM4(bfr[g], sB + bRowOff + (uint32_t)(g * 16 * PITCH * 2) + ks * 32);
#pragma unroll
            for (int mi = 0; mi < 4; mi++) {
#pragma unroll
                for (int nj = 0; nj < 4; nj++) {
                    mma16816(acc[mi][nj], afr[mi], bfr[nj >> 1][(nj & 1) * 2],
                             bfr[nj >> 1][(nj & 1) * 2 + 1]);
                }
            }
        }

        CPA_WAIT(STAGES - 2);
        __syncthreads();
    }

    // ---------------- epilogue: scale + quantized bias + relu ----------------
    const float inv127 = 1.0f / 127.0f;
    int grow0 = ctaM + warp_m + (lane >> 2);
    int gcol0 = ctaN + warp_n + (lane & 3) * 2;

    float2 bq[4];
#pragma unroll
    for (int nj = 0; nj < 4; nj++) {
        int gc = gcol0 + nj * 8;
        float b0 = bias[gc], b1 = bias[gc + 1];
        b0 = fminf(fmaxf(b0, -1.0f), 1.0f);
        b1 = fminf(fmaxf(b1, -1.0f), 1.0f);
        bq[nj].x = rintf(b0 * 127.0f) * inv127;
        bq[nj].y = rintf(b1 * 127.0f) * inv127;
    }

#pragma unroll
    for (int mi = 0; mi < 4; mi++) {
#pragma unroll
        for (int h = 0; h < 2; h++) {
            int grow = grow0 + mi * 16 + h * 8;
            float* orow = out + (size_t)grow * N_DIM;
#pragma unroll
            for (int nj = 0; nj < 4; nj++) {
                float2 v;
                v.x = fmaxf(fmaf(acc[mi][nj][h * 2 + 0], inv127, bq[nj].x), 0.0f);
                v.y = fmaxf(fmaf(acc[mi][nj][h * 2 + 1], inv127, bq[nj].y), 0.0f);
                *reinterpret_cast<float2*>(orow + gcol0 + nj * 8) = v;
            }
        }
    }
}

// ---------------- launch ----------------
extern "C" void kernel_launch(void* const* d_in, const int* in_sizes, int n_in,
                              void* d_out, int out_size) {
    const float* x = (const float*)d_in[0];
    const float* w = (const float*)d_in[1];
    const float* bias = (const float*)d_in[2];
    float* out = (float*)d_out;

    cudaFuncSetAttribute(pwb_gemm_kernel,
                         cudaFuncAttributeMaxDynamicSharedMemorySize, SMEM_TOTAL);

    convert_x_kernel<<<(int)(((size_t)M_DIM * K_DIM) / (256 * 8)), 256>>>(x);
    quant_w_kernel<<<dim3(N_DIM / 64, K_DIM / 64), 256>>>(w);
    pwb_gemm_kernel<<<(M_DIM / BM) * (N_DIM / BN), NTHREADS, SMEM_TOTAL>>>(out, bias);
}

// round 3
// speedup vs baseline: 1.0905x; 1.0905x over previous
#include <cuda_runtime.h>
#include <cuda_fp16.h>
#include <cstdint>
#include <cstddef>

#define DEVI __device__ __forceinline__

static constexpr int M_DIM = 8192;
static constexpr int N_DIM = 4096;
static constexpr int K_DIM = 4096;

static constexpr int BM = 256;
static constexpr int BN = 128;
static constexpr int BK = 64;
static constexpr int NTHREADS = 256;        // 8 warps: 4 in M x 2 in N, warp tile 64x64
static constexpr int STAGES = 4;
static constexpr int NKITER = K_DIM / BK;   // 64

static constexpr int A_STAGE_BYTES = BM * BK * 2;   // 32768 (rows of 128B)
static constexpr int B_STAGE_BYTES = BN * BK * 2;   // 16384
static constexpr int STAGE_BYTES = A_STAGE_BYTES + B_STAGE_BYTES;  // 49152
static constexpr int SMEM_TOTAL = STAGES * STAGE_BYTES;            // 196608

// Scratch: x in fp16, W quantized*127 (exact integer in fp16), transposed to [N,K] K-major.
__device__ __half g_xh[(size_t)M_DIM * K_DIM];
__device__ __half g_wt[(size_t)N_DIM * K_DIM];

// ---------------- helpers ----------------
DEVI uint32_t smem_u32(const void* p) {
    uint32_t a;
    asm("{ .reg .u64 t; cvta.to.shared.u64 t, %1; cvt.u32.u64 %0, t; }" : "=r"(a) : "l"(p));
    return a;
}

#define CPA16(dst, src) \
    asm volatile("cp.async.cg.shared.global [%0], [%1], 16;" :: "r"(dst), "l"(src) : "memory")
#define CPA_COMMIT() asm volatile("cp.async.commit_group;" ::: "memory")
#define CPA_WAIT(n)  asm volatile("cp.async.wait_group %0;" :: "n"(n) : "memory")

#define LDSM4(r, addr) \
    asm volatile("ldmatrix.sync.aligned.m8n8.x4.shared.b16 {%0,%1,%2,%3}, [%4];" \
        : "=r"((r)[0]), "=r"((r)[1]), "=r"((r)[2]), "=r"((r)[3]) : "r"(addr))

DEVI void mma16816(float* c, const uint32_t* a, uint32_t b0, uint32_t b1) {
    asm volatile(
        "mma.sync.aligned.m16n8k16.row.col.f32.f16.f16.f32 "
        "{%0,%1,%2,%3}, {%4,%5,%6,%7}, {%8,%9}, {%0,%1,%2,%3};"
        : "+f"(c[0]), "+f"(c[1]), "+f"(c[2]), "+f"(c[3])
        : "r"(a[0]), "r"(a[1]), "r"(a[2]), "r"(a[3]), "r"(b0), "r"(b1));
}

// ---------------- preprocessing ----------------

__global__ void __launch_bounds__(256) convert_x_kernel(const float* __restrict__ X) {
    size_t i = ((size_t)blockIdx.x * 256 + threadIdx.x) * 8;
    float4 a = *reinterpret_cast<const float4*>(X + i);
    float4 b = *reinterpret_cast<const float4*>(X + i + 4);
    __half2 p0 = __floats2half2_rn(a.x, a.y);
    __half2 p1 = __floats2half2_rn(a.z, a.w);
    __half2 p2 = __floats2half2_rn(b.x, b.y);
    __half2 p3 = __floats2half2_rn(b.z, b.w);
    uint4 u;
    u.x = *reinterpret_cast<uint32_t*>(&p0);
    u.y = *reinterpret_cast<uint32_t*>(&p1);
    u.z = *reinterpret_cast<uint32_t*>(&p2);
    u.w = *reinterpret_cast<uint32_t*>(&p3);
    *reinterpret_cast<uint4*>(g_xh + i) = u;
}

// W [K,N] fp32 -> g_wt [N,K] fp16 = round(clip(w)*127) via smem-tiled transpose
__global__ void __launch_bounds__(256) quant_w_kernel(const float* __restrict__ W) {
    __shared__ __half tile[64][66];
    int t = threadIdx.x;
    int n0 = blockIdx.x * 64;
    int k0 = blockIdx.y * 64;
    int r = t >> 6;
    int c = t & 63;
#pragma unroll
    for (int rr = 0; rr < 16; rr++) {
        int k = r + rr * 4;
        float w = W[(size_t)(k0 + k) * N_DIM + n0 + c];
        w = fminf(fmaxf(w, -1.0f), 1.0f);
        tile[k][c] = __float2half_rn(rintf(w * 127.0f));
    }
    __syncthreads();
#pragma unroll
    for (int ww = 0; ww < 16; ww++) {
        int nl = r + ww * 4;
        g_wt[(size_t)(n0 + nl) * K_DIM + k0 + c] = tile[c][nl];
    }
}

// ---------------- GEMM ----------------

DEVI void load_stage(uint32_t sbase, int buf,
                     const __half* __restrict__ gA, const __half* __restrict__ gB,
                     int k0, int tid) {
    uint32_t sA = sbase + buf * STAGE_BYTES;
    uint32_t sB = sA + A_STAGE_BYTES;
    const __half* a = gA + k0;
    const __half* b = gB + k0;
    // A: 256 rows x 8 16B-chunks = 2048 cp16 / 256 threads = 8 each
#pragma unroll
    for (int i = 0; i < 8; i++) {
        int id = tid + i * NTHREADS;
        int r = id >> 3;
        int c = id & 7;
        uint32_t dst = sA + (uint32_t)(r * 128 + ((c ^ (r & 7)) << 4));
        CPA16(dst, a + (size_t)r * K_DIM + c * 8);
    }
    // B: 128 rows x 8 chunks = 1024 cp16 / 256 = 4 each
#pragma unroll
    for (int i = 0; i < 4; i++) {
        int id = tid + i * NTHREADS;
        int r = id >> 3;
        int c = id & 7;
        uint32_t dst = sB + (uint32_t)(r * 128 + ((c ^ (r & 7)) << 4));
        CPA16(dst, b + (size_t)r * K_DIM + c * 8);
    }
}

__global__ void __launch_bounds__(NTHREADS, 1) pwb_gemm_kernel(
    float* __restrict__ out, const float* __restrict__ bias) {
    extern __shared__ char smem[];
    uint32_t sbase = smem_u32(smem);

    int tid = threadIdx.x;
    int lane = tid & 31;
    int w = tid >> 5;                 // 0..7
    int warp_m = (w >> 1) * 64;       // 4 warps in M
    int warp_n = (w & 1) * 64;        // 2 warps in N

    int ctaM = (int)(blockIdx.x >> 5) * BM;   // 32 M tiles
    int ctaN = (int)(blockIdx.x & 31) * BN;   // 32 N tiles

    const __half* gA = g_xh + (size_t)ctaM * K_DIM;
    const __half* gB = g_wt + (size_t)ctaN * K_DIM;

    // ldmatrix address components (XOR swizzle; row&7 == lane&7 everywhere)
    uint32_t aBase = (uint32_t)(warp_m + (lane & 15)) * 128;            // + mi*2048
    uint32_t bBase = (uint32_t)(warp_n + ((lane >> 4) << 3) + (lane & 7)) * 128;  // + g*2048
    uint32_t swzA[4], swzB[4];
#pragma unroll
    for (int ks = 0; ks < 4; ks++) {
        swzA[ks] = (uint32_t)(((ks * 2 + (lane >> 4)) ^ (lane & 7)) << 4);
        swzB[ks] = (uint32_t)(((ks * 2 + ((lane >> 3) & 1)) ^ (lane & 7)) << 4);
    }

    float acc[4][8][4];
#pragma unroll
    for (int mi = 0; mi < 4; mi++)
#pragma unroll
        for (int nj = 0; nj < 8; nj++)
#pragma unroll
            for (int e = 0; e < 4; e++) acc[mi][nj][e] = 0.0f;

    // prologue: prefetch 3 stages
#pragma unroll
    for (int s = 0; s < STAGES - 1; s++) {
        load_stage(sbase, s, gA, gB, s * BK, tid);
        CPA_COMMIT();
    }
    CPA_WAIT(2);
    __syncthreads();

    uint32_t afr[2][4][4];
    uint32_t bfr[2][4][4];

    for (int it = 0; it < NKITER; it++) {
        int buf = it & (STAGES - 1);
        uint32_t sA = sbase + buf * STAGE_BYTES;
        uint32_t sB = sA + A_STAGE_BYTES;

        // prefetch stage it+3 into buffer (it+3)&3 (freed by compute of it-1 + sync)
        if (it + STAGES - 1 < NKITER) {
            load_stage(sbase, (it + STAGES - 1) & (STAGES - 1), gA, gB,
                       (it + STAGES - 1) * BK, tid);
        }
        CPA_COMMIT();

        // load ks=0 fragments
#pragma unroll
        for (int mi = 0; mi < 4; mi++)
            LDSM4(afr[0][mi], sA + aBase + mi * 2048 + swzA[0]);
#pragma unroll
        for (int g = 0; g < 4; g++)
            LDSM4(bfr[0][g], sB + bBase + g * 2048 + swzB[0]);

#pragma unroll
        for (int ks = 0; ks < 4; ks++) {
            int cur = ks & 1, nxt = cur ^ 1;
            if (ks < 3) {
#pragma unroll
                for (int mi = 0; mi < 4; mi++)
                    LDSM4(afr[nxt][mi], sA + aBase + mi * 2048 + swzA[ks + 1]);
#pragma unroll
                for (int g = 0; g < 4; g++)
                    LDSM4(bfr[nxt][g], sB + bBase + g * 2048 + swzB[ks + 1]);
            }
#pragma unroll
            for (int mi = 0; mi < 4; mi++) {
#pragma unroll
                for (int nj = 0; nj < 8; nj++) {
                    mma16816(acc[mi][nj], afr[cur][mi],
                             bfr[cur][nj >> 1][(nj & 1) * 2],
                             bfr[cur][nj >> 1][(nj & 1) * 2 + 1]);
                }
            }
        }

        CPA_WAIT(2);      // stage it+1 resident
        __syncthreads();
    }

    // ---------------- epilogue: scale + quantized bias + relu ----------------
    const float inv127 = 1.0f / 127.0f;
    int grow0 = ctaM + warp_m + (lane >> 2);
    int gcol0 = ctaN + warp_n + (lane & 3) * 2;

    float2 bq[8];
#pragma unroll
    for (int nj = 0; nj < 8; nj++) {
        int gc = gcol0 + nj * 8;
        float b0 = bias[gc], b1 = bias[gc + 1];
        b0 = fminf(fmaxf(b0, -1.0f), 1.0f);
        b1 = fminf(fmaxf(b1, -1.0f), 1.0f);
        bq[nj].x = rintf(b0 * 127.0f) * inv127;
        bq[nj].y = rintf(b1 * 127.0f) * inv127;
    }

#pragma unroll
    for (int mi = 0; mi < 4; mi++) {
#pragma unroll
        for (int h = 0; h < 2; h++) {
            int grow = grow0 + mi * 16 + h * 8;
            float* orow = out + (size_t)grow * N_DIM;
#pragma unroll
            for (int nj = 0; nj < 8; nj++) {
                float2 v;
                v.x = fmaxf(fmaf(acc[mi][nj][h * 2 + 0], inv127, bq[nj].x), 0.0f);
                v.y = fmaxf(fmaf(acc[mi][nj][h * 2 + 1], inv127, bq[nj].y), 0.0f);
                *reinterpret_cast<float2*>(orow + gcol0 + nj * 8) = v;
            }
        }
    }
}

// ---------------- launch ----------------
extern "C" void kernel_launch(void* const* d_in, const int* in_sizes, int n_in,
                              void* d_out, int out_size) {
    const float* x = (const float*)d_in[0];
    const float* w = (const float*)d_in[1];
    const float* bias = (const float*)d_in[2];
    float* out = (float*)d_out;

    cudaFuncSetAttribute(pwb_gemm_kernel,
                         cudaFuncAttributeMaxDynamicSharedMemorySize, SMEM_TOTAL);

    convert_x_kernel<<<(int)(((size_t)M_DIM * K_DIM) / (256 * 8)), 256>>>(x);
    quant_w_kernel<<<dim3(N_DIM / 64, K_DIM / 64), 256>>>(w);
    pwb_gemm_kernel<<<(M_DIM / BM) * (N_DIM / BN), NTHREADS, SMEM_TOTAL>>>(out, bias);
}